// round 1
// baseline (speedup 1.0000x reference)
#include <cuda_runtime.h>
#include <stdint.h>

#define MAX_NODES 75000
#define F 64

// scratch: aggregated messages per node (float32), zeroed each launch
__device__ float g_agg[(size_t)MAX_NODES * F];

__global__ void zero_agg_kernel(int n4) {
    int i = blockIdx.x * blockDim.x + threadIdx.x;
    if (i < n4) reinterpret_cast<float4*>(g_agg)[i] = make_float4(0.f, 0.f, 0.f, 0.f);
}

// One warp per edge: gather feature[src]*rsqrt(deg[src]) (float2 per lane),
// atomic-add into agg[dst].
__global__ void scatter_kernel(const float* __restrict__ feat,
                               const float* __restrict__ deg,
                               const int*   __restrict__ src,
                               const int*   __restrict__ dst,
                               int E) {
    int w = (int)(((size_t)blockIdx.x * blockDim.x + threadIdx.x) >> 5);
    int lane = threadIdx.x & 31;
    if (w >= E) return;
    int s = __ldg(src + w);
    int d = __ldg(dst + w);
    float isd = rsqrtf(__ldg(deg + s));
    float2 v = __ldg(reinterpret_cast<const float2*>(feat) + (size_t)s * 32 + lane);
    float* o = g_agg + (size_t)d * F + lane * 2;
    atomicAdd(o,     v.x * isd);
    atomicAdd(o + 1, v.y * isd);
}

// out[64-row tile] = (agg * rsqrt(deg)) @ W + b
// 256 threads, each computes a 4x4 micro-tile. A transposed into smem
// (padded to 68 to keep float4 alignment), W row-major in smem.
__global__ void apply_kernel(const float* __restrict__ deg,
                             const float* __restrict__ W,
                             const float* __restrict__ b,
                             float* __restrict__ out,
                             int N) {
    __shared__ float As[64][68];   // As[k][row]
    __shared__ float Ws[64 * 64];  // Ws[k*64 + col]
    __shared__ float bs[64];

    int tid  = threadIdx.x;
    int base = blockIdx.x * 64;

    #pragma unroll
    for (int i = tid; i < 4096; i += 256) Ws[i] = W[i];
    if (tid < 64) bs[tid] = b[tid];

    #pragma unroll
    for (int i = tid; i < 4096; i += 256) {
        int r = i >> 6, c = i & 63;
        int node = base + r;
        float v = 0.f;
        if (node < N) v = g_agg[(size_t)node * F + c] * rsqrtf(__ldg(deg + node));
        As[c][r] = v;
    }
    __syncthreads();

    int tx = tid & 15, ty = tid >> 4;   // tx: output-col group, ty: row group
    float acc[4][4];
    #pragma unroll
    for (int i = 0; i < 4; i++)
        #pragma unroll
        for (int j = 0; j < 4; j++) acc[i][j] = 0.f;

    #pragma unroll
    for (int k = 0; k < 64; k++) {
        float4 a = *reinterpret_cast<const float4*>(&As[k][ty * 4]);
        float4 w = *reinterpret_cast<const float4*>(&Ws[k * 64 + tx * 4]);
        acc[0][0] += a.x * w.x; acc[0][1] += a.x * w.y; acc[0][2] += a.x * w.z; acc[0][3] += a.x * w.w;
        acc[1][0] += a.y * w.x; acc[1][1] += a.y * w.y; acc[1][2] += a.y * w.z; acc[1][3] += a.y * w.w;
        acc[2][0] += a.z * w.x; acc[2][1] += a.z * w.y; acc[2][2] += a.z * w.z; acc[2][3] += a.z * w.w;
        acc[3][0] += a.w * w.x; acc[3][1] += a.w * w.y; acc[3][2] += a.w * w.z; acc[3][3] += a.w * w.w;
    }

    float4 bb = *reinterpret_cast<const float4*>(&bs[tx * 4]);
    #pragma unroll
    for (int i = 0; i < 4; i++) {
        int node = base + ty * 4 + i;
        if (node < N) {
            float4 r4 = make_float4(acc[i][0] + bb.x, acc[i][1] + bb.y,
                                    acc[i][2] + bb.z, acc[i][3] + bb.w);
            *reinterpret_cast<float4*>(out + (size_t)node * F + tx * 4) = r4;
        }
    }
}

extern "C" void kernel_launch(void* const* d_in, const int* in_sizes, int n_in,
                              void* d_out, int out_size) {
    const float* feature = (const float*)d_in[0];
    const float* degree  = (const float*)d_in[1];
    const int*   src     = (const int*)d_in[2];
    const int*   dst     = (const int*)d_in[3];
    const float* W       = (const float*)d_in[4];
    const float* b       = (const float*)d_in[5];
    float* out = (float*)d_out;

    int N = in_sizes[1];        // 75000 nodes
    int E = in_sizes[2];        // 1200000 edges

    int n4 = (N * F) / 4;
    zero_agg_kernel<<<(n4 + 255) / 256, 256>>>(n4);

    // one warp per edge, 8 warps per block
    scatter_kernel<<<(E + 7) / 8, 256>>>(feature, degree, src, dst, E);

    apply_kernel<<<(N + 63) / 64, 256>>>(degree, W, b, out, N);
}